// round 4
// baseline (speedup 1.0000x reference)
#include <cuda_runtime.h>
#include <cuda_bf16.h>

#define NB    4
#define T     4096
#define DIN   1024
#define DHEAD 64
#define MT    (NB*T)
#define PCH   40        // smem pitch in u32 -> conflict-free LDS.64 fragment loads

// Pre-split bf16 planes of x, fragment-ordered: [row][chunk 0..15][32 u32]
__device__ unsigned g_xb[MT*16*32], g_xr[MT*16*32];
// Pre-split W planes: [(mat*64+n)][chunk][32]
__device__ unsigned g_wb[3*64*16*32], g_wr[3*64*16*32];
// Q/K planes, fragment-ordered (32 u32 per row of 64 values)
__device__ unsigned g_qb[MT*32], g_qr[MT*32];
__device__ unsigned g_kb[MT*32], g_kr[MT*32];
// V transposed: [b][dim 0..63][T/2 u32 key-pairs], frag-ordered per 64-key tile
__device__ unsigned g_vtb[NB*64*(T/2)], g_vtr[NB*64*(T/2)];

// ---------------------------------------------------------------------------
// helpers
// ---------------------------------------------------------------------------
__device__ __forceinline__ int slotf(int p) {   // value-pair p -> frag slot
    return ((p >> 3) << 3) + ((p & 3) << 1) + ((p >> 2) & 1);
}
__device__ __forceinline__ int islot(int s) {   // frag slot -> value-pair
    int w = s & 7;
    return ((s >> 3) << 3) + ((w & 1) ? 4 + (w >> 1) : (w >> 1));
}

__device__ __forceinline__ void mma16816(float&c0,float&c1,float&c2,float&c3,
                                         unsigned a0,unsigned a1,unsigned a2,unsigned a3,
                                         unsigned b0,unsigned b1)
{
    asm volatile("mma.sync.aligned.m16n8k16.row.col.f32.bf16.bf16.f32 "
        "{%0,%1,%2,%3},{%4,%5,%6,%7},{%8,%9},{%0,%1,%2,%3};"
        : "+f"(c0),"+f"(c1),"+f"(c2),"+f"(c3)
        : "r"(a0),"r"(a1),"r"(a2),"r"(a3),"r"(b0),"r"(b1));
}

__device__ __forceinline__ void split2(float lo, float hi, unsigned &b, unsigned &r)
{
    asm("cvt.rn.bf16x2.f32 %0, %1, %2;" : "=r"(b) : "f"(hi), "f"(lo));
    __nv_bfloat162 h2 = *reinterpret_cast<__nv_bfloat162*>(&b);
    float blo = __bfloat162float(h2.x);
    float bhi = __bfloat162float(h2.y);
    asm("cvt.rn.bf16x2.f32 %0, %1, %2;" : "=r"(r) : "f"(hi-bhi), "f"(lo-blo));
}

__device__ __forceinline__ unsigned prmtf(unsigned a, unsigned b, unsigned sel)
{
    unsigned d;
    asm("prmt.b32 %0,%1,%2,%3;" : "=r"(d) : "r"(a), "r"(b), "r"(sel));
    return d;
}

__device__ __forceinline__ void cp16(unsigned dst, const void* src)
{
    asm volatile("cp.async.cg.shared.global [%0],[%1],16;" :: "r"(dst), "l"(src));
}
__device__ __forceinline__ unsigned smem_u32(const void* p)
{
    unsigned a;
    asm("{.reg .u64 t; cvta.to.shared.u64 t, %1; cvt.u32.u64 %0, t;}" : "=r"(a) : "l"(p));
    return a;
}

// ---------------------------------------------------------------------------
// Kernel 0: streaming pre-split of x (and W) into frag-ordered bf16 planes.
// grid (MT/8 + 24), block 256. Warp w handles row blockIdx.x*8 + w, 16 chunks.
// ---------------------------------------------------------------------------
__global__ __launch_bounds__(256) void split_kernel(
    const float* __restrict__ x,
    const float* __restrict__ Wk, const float* __restrict__ Wq,
    const float* __restrict__ Wv)
{
    const int tid  = threadIdx.x;
    const int lane = tid & 31;
    const int R    = blockIdx.x * 8 + (tid >> 5);

    const float* src;
    unsigned *db, *dr;
    if (R < MT) {
        src = x + (size_t)R * DIN;
        db = g_xb + (size_t)R * 512;
        dr = g_xr + (size_t)R * 512;
    } else {
        int r2  = R - MT;                 // [0,192)
        int mat = r2 >> 6, n = r2 & 63;
        src = ((mat == 0) ? Wk : (mat == 1) ? Wq : Wv) + (size_t)n * DIN;
        db = g_wb + (size_t)r2 * 512;
        dr = g_wr + (size_t)r2 * 512;
    }

    const int p = islot(lane);            // value pair this lane emits
    #pragma unroll
    for (int c = 0; c < 16; c++) {
        float2 v = *(const float2*)&src[c*64 + 2*p];
        unsigned b, r;
        split2(v.x, v.y, b, r);
        db[c*32 + lane] = b;
        dr[c*32 + lane] = r;
    }
}

// ---------------------------------------------------------------------------
// Kernel 1: QKV projection (split-bf16 mma). Producers are pure cp.async of
// pre-split fragment rows. grid (3, MT/128), block 256 (8 warps x 16 rows).
// smem rows stacked: Xb[0..127], Xr[128..255], Wb[256..319], Wr[320..383].
// ---------------------------------------------------------------------------
#define QKV_SMEM (384 * PCH * 4)   // 61440 B

__global__ __launch_bounds__(256) void qkv_kernel(
    const float* __restrict__ bk, const float* __restrict__ bq,
    const float* __restrict__ bv)
{
    extern __shared__ unsigned smu[];
    const unsigned sbase = smem_u32(smu);

    const int mat = blockIdx.x;
    const float* bias = (mat == 0) ? bk : (mat == 1) ? bq : bv;

    const int m0   = blockIdx.y * 128;
    const int tid  = threadIdx.x;
    const int lane = tid & 31;
    const int g    = lane >> 2;
    const int q    = lane & 3;
    const int wrow = (tid >> 5) * 16;

    // producer mapping: 384 rows of 128B per chunk; thread handles idx, idx+256
    const unsigned* psrc[2]; unsigned pdst[2]; bool pact[2];
    #pragma unroll
    for (int rr = 0; rr < 2; rr++) {
        int idx = tid + 256*rr;
        pact[rr] = (idx < 384);
        int i2 = pact[rr] ? idx : 0;
        const unsigned* s;
        if      (i2 < 128) s = g_xb + ((size_t)(m0 + i2      )*16)*32;
        else if (i2 < 256) s = g_xr + ((size_t)(m0 + i2 - 128)*16)*32;
        else if (i2 < 320) s = g_wb + ((size_t)(mat*64 + i2 - 256)*16)*32;
        else               s = g_wr + ((size_t)(mat*64 + i2 - 320)*16)*32;
        psrc[rr] = s;
        pdst[rr] = sbase + (unsigned)i2 * (PCH*4);
    }

    #define QISSUE(c) do {                                                      \
        _Pragma("unroll")                                                        \
        for (int rr_ = 0; rr_ < 2; rr_++) if (pact[rr_]) {                      \
            const unsigned* sp_ = psrc[rr_] + (c)*32;                           \
            _Pragma("unroll")                                                    \
            for (int i_ = 0; i_ < 8; i_++) cp16(pdst[rr_] + i_*16u, sp_ + i_*4);\
        }                                                                        \
        asm volatile("cp.async.commit_group;");                                 \
    } while (0)

    const unsigned* Xb = smu;
    const unsigned* Xr = smu + 128*PCH;
    const unsigned* Wb = smu + 256*PCH;
    const unsigned* Wr = smu + 320*PCH;

    float acc[8][4];
    #pragma unroll
    for (int j = 0; j < 8; j++)
        #pragma unroll
        for (int c = 0; c < 4; c++) acc[j][c] = 0.f;

    QISSUE(0);
    for (int c = 0; c < 16; c++) {
        asm volatile("cp.async.wait_group 0;");
        __syncthreads();

        #pragma unroll
        for (int ks = 0; ks < 4; ks++) {
            const int a0 = (wrow+g)*PCH + ks*8 + q*2;
            uint2 xAb = *(const uint2*)&Xb[a0];
            uint2 xBb = *(const uint2*)&Xb[a0 + 8*PCH];
            uint2 xAr = *(const uint2*)&Xr[a0];
            uint2 xBr = *(const uint2*)&Xr[a0 + 8*PCH];
            #pragma unroll
            for (int jn = 0; jn < 8; jn++) {
                const int bbo = (jn*8+g)*PCH + ks*8 + q*2;
                uint2 wb = *(const uint2*)&Wb[bbo];
                uint2 wr = *(const uint2*)&Wr[bbo];
                mma16816(acc[jn][0],acc[jn][1],acc[jn][2],acc[jn][3],
                         xAb.x,xBb.x,xAb.y,xBb.y, wb.x,wb.y);
                mma16816(acc[jn][0],acc[jn][1],acc[jn][2],acc[jn][3],
                         xAb.x,xBb.x,xAb.y,xBb.y, wr.x,wr.y);
                mma16816(acc[jn][0],acc[jn][1],acc[jn][2],acc[jn][3],
                         xAr.x,xBr.x,xAr.y,xBr.y, wb.x,wb.y);
            }
        }
        __syncthreads();
        if (c < 15) QISSUE(c+1);
    }

    // epilogue: bias + relu, pre-split store (Q scaled by 1/8)
    const float qscale = (mat == 1) ? 0.125f : 1.0f;
    #pragma unroll
    for (int jn = 0; jn < 8; jn++) {
        int col = jn*8 + q*2;
        float2 bb = *(const float2*)&bias[col];
        float o0 = fmaxf(acc[jn][0]+bb.x, 0.f) * qscale;
        float o1 = fmaxf(acc[jn][1]+bb.y, 0.f) * qscale;
        float o2 = fmaxf(acc[jn][2]+bb.x, 0.f) * qscale;
        float o3 = fmaxf(acc[jn][3]+bb.y, 0.f) * qscale;
        unsigned vb0, vr0, vb1, vr1;
        split2(o0, o1, vb0, vr0);
        split2(o2, o3, vb1, vr1);

        if (mat != 2) {
            unsigned* pb = (mat == 0) ? g_kb : g_qb;
            unsigned* pr = (mat == 0) ? g_kr : g_qr;
            int sl = slotf(jn*4 + q);
            size_t r0 = (size_t)(m0 + wrow + g);
            pb[r0*32 + sl]     = vb0;  pr[r0*32 + sl]     = vr0;
            pb[(r0+8)*32 + sl] = vb1;  pr[(r0+8)*32 + sl] = vr1;
        } else {
            unsigned ob0 = __shfl_xor_sync(0xffffffffu, vb0, 4);
            unsigned or0 = __shfl_xor_sync(0xffffffffu, vr0, 4);
            unsigned ob1 = __shfl_xor_sync(0xffffffffu, vb1, 4);
            unsigned or1 = __shfl_xor_sync(0xffffffffu, vr1, 4);
            unsigned rb0, rr0, rb1, rr1;
            if ((g & 1) == 0) {
                rb0 = prmtf(vb0, ob0, 0x5410); rr0 = prmtf(vr0, or0, 0x5410);
                rb1 = prmtf(vb1, ob1, 0x5410); rr1 = prmtf(vr1, or1, 0x5410);
            } else {
                rb0 = prmtf(ob0, vb0, 0x7632); rr0 = prmtf(or0, vr0, 0x7632);
                rb1 = prmtf(ob1, vb1, 0x7632); rr1 = prmtf(or1, vr1, 0x7632);
            }
            int d     = jn*8 + q*2 + (g & 1);
            int brow  = m0 / T;
            int base0 = (m0 & (T-1)) + wrow + (g & ~1);
            int tile  = base0 >> 6;
            int p0    = (base0 & 63) >> 1;
            size_t idx0 = ((size_t)(brow*64 + d))*(T/2) + tile*32 + slotf(p0);
            size_t idx1 = ((size_t)(brow*64 + d))*(T/2) + tile*32 + slotf(p0 + 4);
            g_vtb[idx0] = rb0;  g_vtr[idx0] = rr0;
            g_vtb[idx1] = rb1;  g_vtr[idx1] = rr1;
        }
    }
    #undef QISSUE
}

// ---------------------------------------------------------------------------
// Kernel 2: flash attention. 64 queries/CTA, block 128 (4 warps), grid
// (T/64, NB) = 256 CTAs -> 2 CTAs/SM. Double-buffered cp.async K/V.
// ---------------------------------------------------------------------------
#define AQ     64
#define ASTAGE (4*64*PCH)               // u32 per stage
#define ATTN_SMEM (2*ASTAGE*4)          // 81920 B

__global__ __launch_bounds__(128) void attn_kernel(float* __restrict__ out)
{
    extern __shared__ unsigned smu[];
    const unsigned sbase = smem_u32(smu);

    const int b    = blockIdx.y;
    const int q0   = blockIdx.x * AQ;
    const int tid  = threadIdx.x;
    const int lane = tid & 31;
    const int g    = lane >> 2;
    const int q    = lane & 3;
    const int wrow = (tid >> 5) * 16;

    // producer mapping: 256 rows (Kb,Kr,Vtb,Vtr x 64), 2 rows per thread
    const unsigned* psrc[2]; unsigned pdst[2]; int parr[2];
    #pragma unroll
    for (int rr = 0; rr < 2; rr++) {
        int idx = tid + 128*rr;
        int arr = idx >> 6, row = idx & 63;
        parr[rr] = arr;
        if      (arr == 0) psrc[rr] = g_kb  + ((size_t)(b*T) + row)*32;
        else if (arr == 1) psrc[rr] = g_kr  + ((size_t)(b*T) + row)*32;
        else if (arr == 2) psrc[rr] = g_vtb + ((size_t)(b*64 + row))*(T/2);
        else               psrc[rr] = g_vtr + ((size_t)(b*64 + row))*(T/2);
        pdst[rr] = (unsigned)idx * (PCH*4);
    }

    #define ISSUE(kt, stg) do {                                                 \
        _Pragma("unroll")                                                        \
        for (int rr_ = 0; rr_ < 2; rr_++) {                                     \
            const unsigned* sp_ = (parr[rr_] < 2) ? (psrc[rr_] + (size_t)(kt)*32)\
                                                  : (psrc[rr_] + (kt)/2);       \
            unsigned d_ = sbase + (unsigned)(stg)*(ASTAGE*4u) + pdst[rr_];      \
            _Pragma("unroll")                                                    \
            for (int i_ = 0; i_ < 8; i_++) cp16(d_ + i_*16u, sp_ + i_*4);       \
        }                                                                        \
        asm volatile("cp.async.commit_group;");                                 \
    } while (0)

    // Q fragments -> registers (loop-invariant)
    unsigned qb0[4],qb1[4],qb2[4],qb3[4], qr0[4],qr1[4],qr2[4],qr3[4];
    {
        ISSUE(0, 0);
        const size_t r0 = (size_t)(b*T + q0 + wrow + g);
        #pragma unroll
        for (int ks = 0; ks < 4; ks++) {
            uint2 a  = *(const uint2*)&g_qb[r0*32     + ks*8 + q*2];
            uint2 c  = *(const uint2*)&g_qb[(r0+8)*32 + ks*8 + q*2];
            qb0[ks]=a.x; qb2[ks]=a.y; qb1[ks]=c.x; qb3[ks]=c.y;
            uint2 ar = *(const uint2*)&g_qr[r0*32     + ks*8 + q*2];
            uint2 cr = *(const uint2*)&g_qr[(r0+8)*32 + ks*8 + q*2];
            qr0[ks]=ar.x; qr2[ks]=ar.y; qr1[ks]=cr.x; qr3[ks]=cr.y;
        }
    }

    float oacc[8][4];
    #pragma unroll
    for (int j = 0; j < 8; j++)
        #pragma unroll
        for (int c = 0; c < 4; c++) oacc[j][c] = 0.f;
    float m0 = -1e30f, m1 = -1e30f, l0 = 0.f, l1 = 0.f;

    int stg = 0;
    for (int kt = 0; kt < T; kt += 64) {
        if (kt + 64 < T) ISSUE(kt + 64, stg ^ 1);
        asm volatile("cp.async.wait_group 1;");
        __syncthreads();

        unsigned* Kb = smu + stg*ASTAGE;
        unsigned* Kr = Kb + 64*PCH;
        unsigned* Vb = Kb + 128*PCH;
        unsigned* Vr = Kb + 192*PCH;

        // S = Q K^T (bb + br + rb)
        float s[8][4];
        #pragma unroll
        for (int j = 0; j < 8; j++)
            #pragma unroll
            for (int c = 0; c < 4; c++) s[j][c] = 0.f;

        #pragma unroll
        for (int ks = 0; ks < 4; ks++) {
            #pragma unroll
            for (int jn = 0; jn < 8; jn++) {
                const int bbo = (jn*8+g)*PCH + ks*8 + q*2;
                uint2 kb = *(const uint2*)&Kb[bbo];
                uint2 kr = *(const uint2*)&Kr[bbo];
                mma16816(s[jn][0],s[jn][1],s[jn][2],s[jn][3],
                         qb0[ks],qb1[ks],qb2[ks],qb3[ks], kb.x,kb.y);
                mma16816(s[jn][0],s[jn][1],s[jn][2],s[jn][3],
                         qb0[ks],qb1[ks],qb2[ks],qb3[ks], kr.x,kr.y);
                mma16816(s[jn][0],s[jn][1],s[jn][2],s[jn][3],
                         qr0[ks],qr1[ks],qr2[ks],qr3[ks], kb.x,kb.y);
            }
        }

        // online softmax
        float mx0 = -1e30f, mx1 = -1e30f;
        #pragma unroll
        for (int j = 0; j < 8; j++) {
            mx0 = fmaxf(mx0, fmaxf(s[j][0], s[j][1]));
            mx1 = fmaxf(mx1, fmaxf(s[j][2], s[j][3]));
        }
        mx0 = fmaxf(mx0, __shfl_xor_sync(0xffffffffu, mx0, 1));
        mx0 = fmaxf(mx0, __shfl_xor_sync(0xffffffffu, mx0, 2));
        mx1 = fmaxf(mx1, __shfl_xor_sync(0xffffffffu, mx1, 1));
        mx1 = fmaxf(mx1, __shfl_xor_sync(0xffffffffu, mx1, 2));
        float mn0 = fmaxf(m0, mx0), mn1 = fmaxf(m1, mx1);
        float al0 = __expf(m0 - mn0), al1 = __expf(m1 - mn1);
        m0 = mn0; m1 = mn1;

        float sum0 = 0.f, sum1 = 0.f;
        #pragma unroll
        for (int j = 0; j < 8; j++) {
            s[j][0] = __expf(s[j][0] - mn0);
            s[j][1] = __expf(s[j][1] - mn0);
            s[j][2] = __expf(s[j][2] - mn1);
            s[j][3] = __expf(s[j][3] - mn1);
            sum0 += s[j][0] + s[j][1];
            sum1 += s[j][2] + s[j][3];
        }
        sum0 += __shfl_xor_sync(0xffffffffu, sum0, 1);
        sum0 += __shfl_xor_sync(0xffffffffu, sum0, 2);
        sum1 += __shfl_xor_sync(0xffffffffu, sum1, 1);
        sum1 += __shfl_xor_sync(0xffffffffu, sum1, 2);
        l0 = l0*al0 + sum0;
        l1 = l1*al1 + sum1;
        #pragma unroll
        for (int j = 0; j < 8; j++) {
            oacc[j][0]*=al0; oacc[j][1]*=al0; oacc[j][2]*=al1; oacc[j][3]*=al1;
        }

        // O += P V
        #pragma unroll
        for (int kp = 0; kp < 4; kp++) {
            unsigned pb0,pr0,pb1,pr1,pb2,pr2,pb3,pr3;
            split2(s[2*kp  ][0], s[2*kp  ][1], pb0, pr0);
            split2(s[2*kp  ][2], s[2*kp  ][3], pb1, pr1);
            split2(s[2*kp+1][0], s[2*kp+1][1], pb2, pr2);
            split2(s[2*kp+1][2], s[2*kp+1][3], pb3, pr3);
            #pragma unroll
            for (int jn = 0; jn < 8; jn++) {
                const int vbo = (jn*8+g)*PCH + kp*8 + q*2;
                uint2 vb = *(const uint2*)&Vb[vbo];
                uint2 vr = *(const uint2*)&Vr[vbo];
                mma16816(oacc[jn][0],oacc[jn][1],oacc[jn][2],oacc[jn][3],
                         pb0,pb1,pb2,pb3, vb.x,vb.y);
                mma16816(oacc[jn][0],oacc[jn][1],oacc[jn][2],oacc[jn][3],
                         pb0,pb1,pb2,pb3, vr.x,vr.y);
                mma16816(oacc[jn][0],oacc[jn][1],oacc[jn][2],oacc[jn][3],
                         pr0,pr1,pr2,pr3, vb.x,vb.y);
            }
        }
        __syncthreads();
        stg ^= 1;
    }

    float inv0 = 1.f / l0, inv1 = 1.f / l1;
    float* Og = out + ((size_t)b*T + q0)*DHEAD;
    #pragma unroll
    for (int jn = 0; jn < 8; jn++) {
        int col = jn*8 + q*2;
        int r0 = wrow + g;
        float2 o0 = make_float2(oacc[jn][0]*inv0, oacc[jn][1]*inv0);
        float2 o1 = make_float2(oacc[jn][2]*inv1, oacc[jn][3]*inv1);
        *(float2*)&Og[(size_t)r0*DHEAD + col]     = o0;
        *(float2*)&Og[(size_t)(r0+8)*DHEAD + col] = o1;
    }
    #undef ISSUE
}

// ---------------------------------------------------------------------------
extern "C" void kernel_launch(void* const* d_in, const int* in_sizes, int n_in,
                              void* d_out, int out_size)
{
    const float* x  = (const float*)d_in[0];
    const float* Wk = (const float*)d_in[1];
    const float* bk = (const float*)d_in[2];
    const float* Wq = (const float*)d_in[3];
    const float* bq = (const float*)d_in[4];
    const float* Wv = (const float*)d_in[5];
    const float* bv = (const float*)d_in[6];
    float* out = (float*)d_out;

    cudaFuncSetAttribute(qkv_kernel,
                         cudaFuncAttributeMaxDynamicSharedMemorySize, QKV_SMEM);
    cudaFuncSetAttribute(attn_kernel,
                         cudaFuncAttributeMaxDynamicSharedMemorySize, ATTN_SMEM);

    split_kernel<<<MT/8 + 24, 256>>>(x, Wk, Wq, Wv);

    dim3 g1(3, MT / 128);
    qkv_kernel<<<g1, 256, QKV_SMEM>>>(bk, bq, bv);

    dim3 g2(T / AQ, NB);
    attn_kernel<<<g2, 128, ATTN_SMEM>>>(out);
}

// round 5
// speedup vs baseline: 1.0019x; 1.0019x over previous
#include <cuda_runtime.h>
#include <cuda_bf16.h>

#define NB    4
#define T     4096
#define DIN   1024
#define DHEAD 64
#define MT    (NB*T)
#define PCH   40        // smem pitch in u32 -> conflict-free LDS.64 fragment loads

// Pre-split bf16 planes of x, fragment-ordered: [row][chunk 0..15][32 u32]
__device__ unsigned g_xb[MT*16*32], g_xr[MT*16*32];
// Pre-split W planes: [(mat*64+n)][chunk][32]
__device__ unsigned g_wb[3*64*16*32], g_wr[3*64*16*32];
// Q/K planes, fragment-ordered (32 u32 per row of 64 values)
__device__ unsigned g_qb[MT*32], g_qr[MT*32];
__device__ unsigned g_kb[MT*32], g_kr[MT*32];
// V transposed: [b][dim 0..63][T/2 u32 key-pairs], frag-ordered per 64-key tile
__device__ unsigned g_vtb[NB*64*(T/2)], g_vtr[NB*64*(T/2)];

// ---------------------------------------------------------------------------
// helpers
// ---------------------------------------------------------------------------
__device__ __forceinline__ int slotf(int p) {   // value-pair p -> frag slot
    return ((p >> 3) << 3) + ((p & 3) << 1) + ((p >> 2) & 1);
}
__device__ __forceinline__ int islot(int s) {   // frag slot -> value-pair
    int w = s & 7;
    return ((s >> 3) << 3) + ((w & 1) ? 4 + (w >> 1) : (w >> 1));
}

__device__ __forceinline__ void mma16816(float&c0,float&c1,float&c2,float&c3,
                                         unsigned a0,unsigned a1,unsigned a2,unsigned a3,
                                         unsigned b0,unsigned b1)
{
    asm volatile("mma.sync.aligned.m16n8k16.row.col.f32.bf16.bf16.f32 "
        "{%0,%1,%2,%3},{%4,%5,%6,%7},{%8,%9},{%0,%1,%2,%3};"
        : "+f"(c0),"+f"(c1),"+f"(c2),"+f"(c3)
        : "r"(a0),"r"(a1),"r"(a2),"r"(a3),"r"(b0),"r"(b1));
}

__device__ __forceinline__ void split2(float lo, float hi, unsigned &b, unsigned &r)
{
    asm("cvt.rn.bf16x2.f32 %0, %1, %2;" : "=r"(b) : "f"(hi), "f"(lo));
    __nv_bfloat162 h2 = *reinterpret_cast<__nv_bfloat162*>(&b);
    float blo = __bfloat162float(h2.x);
    float bhi = __bfloat162float(h2.y);
    asm("cvt.rn.bf16x2.f32 %0, %1, %2;" : "=r"(r) : "f"(hi-bhi), "f"(lo-blo));
}

__device__ __forceinline__ unsigned prmtf(unsigned a, unsigned b, unsigned sel)
{
    unsigned d;
    asm("prmt.b32 %0,%1,%2,%3;" : "=r"(d) : "r"(a), "r"(b), "r"(sel));
    return d;
}

__device__ __forceinline__ void cp16(unsigned dst, const void* src)
{
    asm volatile("cp.async.cg.shared.global [%0],[%1],16;" :: "r"(dst), "l"(src));
}
__device__ __forceinline__ unsigned smem_u32(const void* p)
{
    unsigned a;
    asm("{.reg .u64 t; cvta.to.shared.u64 t, %1; cvt.u32.u64 %0, t;}" : "=r"(a) : "l"(p));
    return a;
}

// ---------------------------------------------------------------------------
// Kernel 0: streaming pre-split of x (and W) into frag-ordered bf16 planes.
// grid (MT/8 + 24), block 256. Warp w handles row blockIdx.x*8 + w, 16 chunks.
// ---------------------------------------------------------------------------
__global__ __launch_bounds__(256) void split_kernel(
    const float* __restrict__ x,
    const float* __restrict__ Wk, const float* __restrict__ Wq,
    const float* __restrict__ Wv)
{
    const int tid  = threadIdx.x;
    const int lane = tid & 31;
    const int R    = blockIdx.x * 8 + (tid >> 5);

    const float* src;
    unsigned *db, *dr;
    if (R < MT) {
        src = x + (size_t)R * DIN;
        db = g_xb + (size_t)R * 512;
        dr = g_xr + (size_t)R * 512;
    } else {
        int r2  = R - MT;                 // [0,192)
        int mat = r2 >> 6, n = r2 & 63;
        src = ((mat == 0) ? Wk : (mat == 1) ? Wq : Wv) + (size_t)n * DIN;
        db = g_wb + (size_t)r2 * 512;
        dr = g_wr + (size_t)r2 * 512;
    }

    const int p = islot(lane);            // value pair this lane emits
    #pragma unroll
    for (int c = 0; c < 16; c++) {
        float2 v = *(const float2*)&src[c*64 + 2*p];
        unsigned b, r;
        split2(v.x, v.y, b, r);
        db[c*32 + lane] = b;
        dr[c*32 + lane] = r;
    }
}

// ---------------------------------------------------------------------------
// Kernel 1: QKV projection (split-bf16 mma). Producers are pure cp.async of
// pre-split fragment rows. grid (3, MT/128), block 256 (8 warps x 16 rows).
// smem rows stacked: Xb[0..127], Xr[128..255], Wb[256..319], Wr[320..383].
// ---------------------------------------------------------------------------
#define QKV_SMEM (384 * PCH * 4)   // 61440 B

__global__ __launch_bounds__(256) void qkv_kernel(
    const float* __restrict__ bk, const float* __restrict__ bq,
    const float* __restrict__ bv)
{
    extern __shared__ unsigned smu[];
    const unsigned sbase = smem_u32(smu);

    const int mat = blockIdx.x;
    const float* bias = (mat == 0) ? bk : (mat == 1) ? bq : bv;

    const int m0   = blockIdx.y * 128;
    const int tid  = threadIdx.x;
    const int lane = tid & 31;
    const int g    = lane >> 2;
    const int q    = lane & 3;
    const int wrow = (tid >> 5) * 16;

    // producer mapping: 384 rows of 128B per chunk; thread handles idx, idx+256
    const unsigned* psrc[2]; unsigned pdst[2]; bool pact[2];
    #pragma unroll
    for (int rr = 0; rr < 2; rr++) {
        int idx = tid + 256*rr;
        pact[rr] = (idx < 384);
        int i2 = pact[rr] ? idx : 0;
        const unsigned* s;
        if      (i2 < 128) s = g_xb + ((size_t)(m0 + i2      )*16)*32;
        else if (i2 < 256) s = g_xr + ((size_t)(m0 + i2 - 128)*16)*32;
        else if (i2 < 320) s = g_wb + ((size_t)(mat*64 + i2 - 256)*16)*32;
        else               s = g_wr + ((size_t)(mat*64 + i2 - 320)*16)*32;
        psrc[rr] = s;
        pdst[rr] = sbase + (unsigned)i2 * (PCH*4);
    }

    #define QISSUE(c) do {                                                      \
        _Pragma("unroll")                                                        \
        for (int rr_ = 0; rr_ < 2; rr_++) if (pact[rr_]) {                      \
            const unsigned* sp_ = psrc[rr_] + (c)*32;                           \
            _Pragma("unroll")                                                    \
            for (int i_ = 0; i_ < 8; i_++) cp16(pdst[rr_] + i_*16u, sp_ + i_*4);\
        }                                                                        \
        asm volatile("cp.async.commit_group;");                                 \
    } while (0)

    const unsigned* Xb = smu;
    const unsigned* Xr = smu + 128*PCH;
    const unsigned* Wb = smu + 256*PCH;
    const unsigned* Wr = smu + 320*PCH;

    float acc[8][4];
    #pragma unroll
    for (int j = 0; j < 8; j++)
        #pragma unroll
        for (int c = 0; c < 4; c++) acc[j][c] = 0.f;

    QISSUE(0);
    for (int c = 0; c < 16; c++) {
        asm volatile("cp.async.wait_group 0;");
        __syncthreads();

        #pragma unroll
        for (int ks = 0; ks < 4; ks++) {
            const int a0 = (wrow+g)*PCH + ks*8 + q*2;
            uint2 xAb = *(const uint2*)&Xb[a0];
            uint2 xBb = *(const uint2*)&Xb[a0 + 8*PCH];
            uint2 xAr = *(const uint2*)&Xr[a0];
            uint2 xBr = *(const uint2*)&Xr[a0 + 8*PCH];
            #pragma unroll
            for (int jn = 0; jn < 8; jn++) {
                const int bbo = (jn*8+g)*PCH + ks*8 + q*2;
                uint2 wb = *(const uint2*)&Wb[bbo];
                uint2 wr = *(const uint2*)&Wr[bbo];
                mma16816(acc[jn][0],acc[jn][1],acc[jn][2],acc[jn][3],
                         xAb.x,xBb.x,xAb.y,xBb.y, wb.x,wb.y);
                mma16816(acc[jn][0],acc[jn][1],acc[jn][2],acc[jn][3],
                         xAb.x,xBb.x,xAb.y,xBb.y, wr.x,wr.y);
                mma16816(acc[jn][0],acc[jn][1],acc[jn][2],acc[jn][3],
                         xAr.x,xBr.x,xAr.y,xBr.y, wb.x,wb.y);
            }
        }
        __syncthreads();
        if (c < 15) QISSUE(c+1);
    }

    // epilogue: bias + relu, pre-split store (Q scaled by 1/8)
    const float qscale = (mat == 1) ? 0.125f : 1.0f;
    #pragma unroll
    for (int jn = 0; jn < 8; jn++) {
        int col = jn*8 + q*2;
        float2 bb = *(const float2*)&bias[col];
        float o0 = fmaxf(acc[jn][0]+bb.x, 0.f) * qscale;
        float o1 = fmaxf(acc[jn][1]+bb.y, 0.f) * qscale;
        float o2 = fmaxf(acc[jn][2]+bb.x, 0.f) * qscale;
        float o3 = fmaxf(acc[jn][3]+bb.y, 0.f) * qscale;
        unsigned vb0, vr0, vb1, vr1;
        split2(o0, o1, vb0, vr0);
        split2(o2, o3, vb1, vr1);

        if (mat != 2) {
            unsigned* pb = (mat == 0) ? g_kb : g_qb;
            unsigned* pr = (mat == 0) ? g_kr : g_qr;
            int sl = slotf(jn*4 + q);
            size_t r0 = (size_t)(m0 + wrow + g);
            pb[r0*32 + sl]     = vb0;  pr[r0*32 + sl]     = vr0;
            pb[(r0+8)*32 + sl] = vb1;  pr[(r0+8)*32 + sl] = vr1;
        } else {
            unsigned ob0 = __shfl_xor_sync(0xffffffffu, vb0, 4);
            unsigned or0 = __shfl_xor_sync(0xffffffffu, vr0, 4);
            unsigned ob1 = __shfl_xor_sync(0xffffffffu, vb1, 4);
            unsigned or1 = __shfl_xor_sync(0xffffffffu, vr1, 4);
            unsigned rb0, rr0, rb1, rr1;
            if ((g & 1) == 0) {
                rb0 = prmtf(vb0, ob0, 0x5410); rr0 = prmtf(vr0, or0, 0x5410);
                rb1 = prmtf(vb1, ob1, 0x5410); rr1 = prmtf(vr1, or1, 0x5410);
            } else {
                rb0 = prmtf(ob0, vb0, 0x7632); rr0 = prmtf(or0, vr0, 0x7632);
                rb1 = prmtf(ob1, vb1, 0x7632); rr1 = prmtf(or1, vr1, 0x7632);
            }
            int d     = jn*8 + q*2 + (g & 1);
            int brow  = m0 / T;
            int base0 = (m0 & (T-1)) + wrow + (g & ~1);
            int tile  = base0 >> 6;
            int p0    = (base0 & 63) >> 1;
            size_t idx0 = ((size_t)(brow*64 + d))*(T/2) + tile*32 + slotf(p0);
            size_t idx1 = ((size_t)(brow*64 + d))*(T/2) + tile*32 + slotf(p0 + 4);
            g_vtb[idx0] = rb0;  g_vtr[idx0] = rr0;
            g_vtb[idx1] = rb1;  g_vtr[idx1] = rr1;
        }
    }
    #undef QISSUE
}

// ---------------------------------------------------------------------------
// Kernel 2: flash attention. 64 queries/CTA, block 128 (4 warps), grid
// (T/64, NB) = 256 CTAs -> 2 CTAs/SM. Double-buffered cp.async K/V.
// ---------------------------------------------------------------------------
#define AQ     64
#define ASTAGE (4*64*PCH)               // u32 per stage
#define ATTN_SMEM (2*ASTAGE*4)          // 81920 B

__global__ __launch_bounds__(128) void attn_kernel(float* __restrict__ out)
{
    extern __shared__ unsigned smu[];
    const unsigned sbase = smem_u32(smu);

    const int b    = blockIdx.y;
    const int q0   = blockIdx.x * AQ;
    const int tid  = threadIdx.x;
    const int lane = tid & 31;
    const int g    = lane >> 2;
    const int q    = lane & 3;
    const int wrow = (tid >> 5) * 16;

    // producer mapping: 256 rows (Kb,Kr,Vtb,Vtr x 64), 2 rows per thread
    const unsigned* psrc[2]; unsigned pdst[2]; int parr[2];
    #pragma unroll
    for (int rr = 0; rr < 2; rr++) {
        int idx = tid + 128*rr;
        int arr = idx >> 6, row = idx & 63;
        parr[rr] = arr;
        if      (arr == 0) psrc[rr] = g_kb  + ((size_t)(b*T) + row)*32;
        else if (arr == 1) psrc[rr] = g_kr  + ((size_t)(b*T) + row)*32;
        else if (arr == 2) psrc[rr] = g_vtb + ((size_t)(b*64 + row))*(T/2);
        else               psrc[rr] = g_vtr + ((size_t)(b*64 + row))*(T/2);
        pdst[rr] = (unsigned)idx * (PCH*4);
    }

    #define ISSUE(kt, stg) do {                                                 \
        _Pragma("unroll")                                                        \
        for (int rr_ = 0; rr_ < 2; rr_++) {                                     \
            const unsigned* sp_ = (parr[rr_] < 2) ? (psrc[rr_] + (size_t)(kt)*32)\
                                                  : (psrc[rr_] + (kt)/2);       \
            unsigned d_ = sbase + (unsigned)(stg)*(ASTAGE*4u) + pdst[rr_];      \
            _Pragma("unroll")                                                    \
            for (int i_ = 0; i_ < 8; i_++) cp16(d_ + i_*16u, sp_ + i_*4);       \
        }                                                                        \
        asm volatile("cp.async.commit_group;");                                 \
    } while (0)

    // Q fragments -> registers (loop-invariant)
    unsigned qb0[4],qb1[4],qb2[4],qb3[4], qr0[4],qr1[4],qr2[4],qr3[4];
    {
        ISSUE(0, 0);
        const size_t r0 = (size_t)(b*T + q0 + wrow + g);
        #pragma unroll
        for (int ks = 0; ks < 4; ks++) {
            uint2 a  = *(const uint2*)&g_qb[r0*32     + ks*8 + q*2];
            uint2 c  = *(const uint2*)&g_qb[(r0+8)*32 + ks*8 + q*2];
            qb0[ks]=a.x; qb2[ks]=a.y; qb1[ks]=c.x; qb3[ks]=c.y;
            uint2 ar = *(const uint2*)&g_qr[r0*32     + ks*8 + q*2];
            uint2 cr = *(const uint2*)&g_qr[(r0+8)*32 + ks*8 + q*2];
            qr0[ks]=ar.x; qr2[ks]=ar.y; qr1[ks]=cr.x; qr3[ks]=cr.y;
        }
    }

    float oacc[8][4];
    #pragma unroll
    for (int j = 0; j < 8; j++)
        #pragma unroll
        for (int c = 0; c < 4; c++) oacc[j][c] = 0.f;
    float m0 = -1e30f, m1 = -1e30f, l0 = 0.f, l1 = 0.f;

    int stg = 0;
    for (int kt = 0; kt < T; kt += 64) {
        if (kt + 64 < T) ISSUE(kt + 64, stg ^ 1);
        asm volatile("cp.async.wait_group 1;");
        __syncthreads();

        unsigned* Kb = smu + stg*ASTAGE;
        unsigned* Kr = Kb + 64*PCH;
        unsigned* Vb = Kb + 128*PCH;
        unsigned* Vr = Kb + 192*PCH;

        // S = Q K^T (bb + br + rb)
        float s[8][4];
        #pragma unroll
        for (int j = 0; j < 8; j++)
            #pragma unroll
            for (int c = 0; c < 4; c++) s[j][c] = 0.f;

        #pragma unroll
        for (int ks = 0; ks < 4; ks++) {
            #pragma unroll
            for (int jn = 0; jn < 8; jn++) {
                const int bbo = (jn*8+g)*PCH + ks*8 + q*2;
                uint2 kb = *(const uint2*)&Kb[bbo];
                uint2 kr = *(const uint2*)&Kr[bbo];
                mma16816(s[jn][0],s[jn][1],s[jn][2],s[jn][3],
                         qb0[ks],qb1[ks],qb2[ks],qb3[ks], kb.x,kb.y);
                mma16816(s[jn][0],s[jn][1],s[jn][2],s[jn][3],
                         qb0[ks],qb1[ks],qb2[ks],qb3[ks], kr.x,kr.y);
                mma16816(s[jn][0],s[jn][1],s[jn][2],s[jn][3],
                         qr0[ks],qr1[ks],qr2[ks],qr3[ks], kb.x,kb.y);
            }
        }

        // online softmax
        float mx0 = -1e30f, mx1 = -1e30f;
        #pragma unroll
        for (int j = 0; j < 8; j++) {
            mx0 = fmaxf(mx0, fmaxf(s[j][0], s[j][1]));
            mx1 = fmaxf(mx1, fmaxf(s[j][2], s[j][3]));
        }
        mx0 = fmaxf(mx0, __shfl_xor_sync(0xffffffffu, mx0, 1));
        mx0 = fmaxf(mx0, __shfl_xor_sync(0xffffffffu, mx0, 2));
        mx1 = fmaxf(mx1, __shfl_xor_sync(0xffffffffu, mx1, 1));
        mx1 = fmaxf(mx1, __shfl_xor_sync(0xffffffffu, mx1, 2));
        float mn0 = fmaxf(m0, mx0), mn1 = fmaxf(m1, mx1);
        float al0 = __expf(m0 - mn0), al1 = __expf(m1 - mn1);
        m0 = mn0; m1 = mn1;

        float sum0 = 0.f, sum1 = 0.f;
        #pragma unroll
        for (int j = 0; j < 8; j++) {
            s[j][0] = __expf(s[j][0] - mn0);
            s[j][1] = __expf(s[j][1] - mn0);
            s[j][2] = __expf(s[j][2] - mn1);
            s[j][3] = __expf(s[j][3] - mn1);
            sum0 += s[j][0] + s[j][1];
            sum1 += s[j][2] + s[j][3];
        }
        sum0 += __shfl_xor_sync(0xffffffffu, sum0, 1);
        sum0 += __shfl_xor_sync(0xffffffffu, sum0, 2);
        sum1 += __shfl_xor_sync(0xffffffffu, sum1, 1);
        sum1 += __shfl_xor_sync(0xffffffffu, sum1, 2);
        l0 = l0*al0 + sum0;
        l1 = l1*al1 + sum1;
        #pragma unroll
        for (int j = 0; j < 8; j++) {
            oacc[j][0]*=al0; oacc[j][1]*=al0; oacc[j][2]*=al1; oacc[j][3]*=al1;
        }

        // O += P V
        #pragma unroll
        for (int kp = 0; kp < 4; kp++) {
            unsigned pb0,pr0,pb1,pr1,pb2,pr2,pb3,pr3;
            split2(s[2*kp  ][0], s[2*kp  ][1], pb0, pr0);
            split2(s[2*kp  ][2], s[2*kp  ][3], pb1, pr1);
            split2(s[2*kp+1][0], s[2*kp+1][1], pb2, pr2);
            split2(s[2*kp+1][2], s[2*kp+1][3], pb3, pr3);
            #pragma unroll
            for (int jn = 0; jn < 8; jn++) {
                const int vbo = (jn*8+g)*PCH + kp*8 + q*2;
                uint2 vb = *(const uint2*)&Vb[vbo];
                uint2 vr = *(const uint2*)&Vr[vbo];
                mma16816(oacc[jn][0],oacc[jn][1],oacc[jn][2],oacc[jn][3],
                         pb0,pb1,pb2,pb3, vb.x,vb.y);
                mma16816(oacc[jn][0],oacc[jn][1],oacc[jn][2],oacc[jn][3],
                         pb0,pb1,pb2,pb3, vr.x,vr.y);
                mma16816(oacc[jn][0],oacc[jn][1],oacc[jn][2],oacc[jn][3],
                         pr0,pr1,pr2,pr3, vb.x,vb.y);
            }
        }
        __syncthreads();
        stg ^= 1;
    }

    float inv0 = 1.f / l0, inv1 = 1.f / l1;
    float* Og = out + ((size_t)b*T + q0)*DHEAD;
    #pragma unroll
    for (int jn = 0; jn < 8; jn++) {
        int col = jn*8 + q*2;
        int r0 = wrow + g;
        float2 o0 = make_float2(oacc[jn][0]*inv0, oacc[jn][1]*inv0);
        float2 o1 = make_float2(oacc[jn][2]*inv1, oacc[jn][3]*inv1);
        *(float2*)&Og[(size_t)r0*DHEAD + col]     = o0;
        *(float2*)&Og[(size_t)(r0+8)*DHEAD + col] = o1;
    }
    #undef ISSUE
}

// ---------------------------------------------------------------------------
extern "C" void kernel_launch(void* const* d_in, const int* in_sizes, int n_in,
                              void* d_out, int out_size)
{
    const float* x  = (const float*)d_in[0];
    const float* Wk = (const float*)d_in[1];
    const float* bk = (const float*)d_in[2];
    const float* Wq = (const float*)d_in[3];
    const float* bq = (const float*)d_in[4];
    const float* Wv = (const float*)d_in[5];
    const float* bv = (const float*)d_in[6];
    float* out = (float*)d_out;

    cudaFuncSetAttribute(qkv_kernel,
                         cudaFuncAttributeMaxDynamicSharedMemorySize, QKV_SMEM);
    cudaFuncSetAttribute(attn_kernel,
                         cudaFuncAttributeMaxDynamicSharedMemorySize, ATTN_SMEM);

    split_kernel<<<MT/8 + 24, 256>>>(x, Wk, Wq, Wv);

    dim3 g1(3, MT / 128);
    qkv_kernel<<<g1, 256, QKV_SMEM>>>(bk, bq, bv);

    dim3 g2(T / AQ, NB);
    attn_kernel<<<g2, 128, ATTN_SMEM>>>(out);
}

// round 6
// speedup vs baseline: 1.1630x; 1.1608x over previous
#include <cuda_runtime.h>
#include <cuda_bf16.h>

#define NB    4
#define T     4096
#define DIN   1024
#define DHEAD 64
#define MT    (NB*T)
#define PCH   40

__device__ unsigned g_xb[MT*16*32], g_xr[MT*16*32];
__device__ unsigned g_wb[3*64*16*32], g_wr[3*64*16*32];
__device__ unsigned g_qb[MT*32], g_qr[MT*32];
__device__ unsigned g_kb[MT*32], g_kr[MT*32];
__device__ unsigned g_vtb[NB*64*(T/2)], g_vtr[NB*64*(T/2)];

__device__ __forceinline__ int slotf(int p) {
    return ((p >> 3) << 3) + ((p & 3) << 1) + ((p >> 2) & 1);
}
__device__ __forceinline__ int islot(int s) {
    int w = s & 7;
    return ((s >> 3) << 3) + ((w & 1) ? 4 + (w >> 1) : (w >> 1));
}
__device__ __forceinline__ void mma16816(float&c0,float&c1,float&c2,float&c3,
                                         unsigned a0,unsigned a1,unsigned a2,unsigned a3,
                                         unsigned b0,unsigned b1)
{
    asm volatile("mma.sync.aligned.m16n8k16.row.col.f32.bf16.bf16.f32 "
        "{%0,%1,%2,%3},{%4,%5,%6,%7},{%8,%9},{%0,%1,%2,%3};"
        : "+f"(c0),"+f"(c1),"+f"(c2),"+f"(c3)
        : "r"(a0),"r"(a1),"r"(a2),"r"(a3),"r"(b0),"r"(b1));
}
__device__ __forceinline__ void split2(float lo, float hi, unsigned &b, unsigned &r)
{
    asm("cvt.rn.bf16x2.f32 %0, %1, %2;" : "=r"(b) : "f"(hi), "f"(lo));
    __nv_bfloat162 h2 = *reinterpret_cast<__nv_bfloat162*>(&b);
    float blo = __bfloat162float(h2.x);
    float bhi = __bfloat162float(h2.y);
    asm("cvt.rn.bf16x2.f32 %0, %1, %2;" : "=r"(r) : "f"(hi-bhi), "f"(lo-blo));
}
__device__ __forceinline__ unsigned prmtf(unsigned a, unsigned b, unsigned sel)
{
    unsigned d;
    asm("prmt.b32 %0,%1,%2,%3;" : "=r"(d) : "r"(a), "r"(b), "r"(sel));
    return d;
}
__device__ __forceinline__ void cp16(unsigned dst, const void* src)
{
    asm volatile("cp.async.cg.shared.global [%0],[%1],16;" :: "r"(dst), "l"(src));
}
__device__ __forceinline__ unsigned smem_u32(const void* p)
{
    unsigned a;
    asm("{.reg .u64 t; cvta.to.shared.u64 t, %1; cvt.u32.u64 %0, t;}" : "=r"(a) : "l"(p));
    return a;
}

// ---------------------------------------------------------------------------
// Kernel 0: streaming pre-split of x / W into frag-ordered bf16 planes.
// ---------------------------------------------------------------------------
__global__ __launch_bounds__(256) void split_kernel(
    const float* __restrict__ x,
    const float* __restrict__ Wk, const float* __restrict__ Wq,
    const float* __restrict__ Wv)
{
    const int tid  = threadIdx.x;
    const int lane = tid & 31;
    const int R    = blockIdx.x * 8 + (tid >> 5);

    const float* src;
    unsigned *db, *dr;
    if (R < MT) {
        src = x + (size_t)R * DIN;
        db = g_xb + (size_t)R * 512;
        dr = g_xr + (size_t)R * 512;
    } else {
        int r2  = R - MT;
        int mat = r2 >> 6, n = r2 & 63;
        src = ((mat == 0) ? Wk : (mat == 1) ? Wq : Wv) + (size_t)n * DIN;
        db = g_wb + (size_t)r2 * 512;
        dr = g_wr + (size_t)r2 * 512;
    }
    const int p = islot(lane);
    #pragma unroll
    for (int c = 0; c < 16; c++) {
        float2 v = *(const float2*)&src[c*64 + 2*p];
        unsigned b, r;
        split2(v.x, v.y, b, r);
        db[c*32 + lane] = b;
        dr[c*32 + lane] = r;
    }
}

// ---------------------------------------------------------------------------
// Kernel 1: QKV projection, TRUE 2-stage cp.async double buffer.
// grid (3, MT/128), block 256.
// ---------------------------------------------------------------------------
#define QST  (384*PCH)              // u32 per stage
#define QKV_SMEM (2*QST*4)          // 122880 B

__global__ __launch_bounds__(256) void qkv_kernel(
    const float* __restrict__ bk, const float* __restrict__ bq,
    const float* __restrict__ bv)
{
    extern __shared__ unsigned smu[];
    const unsigned sbase = smem_u32(smu);

    const int mat = blockIdx.x;
    const float* bias = (mat == 0) ? bk : (mat == 1) ? bq : bv;
    const int m0   = blockIdx.y * 128;
    const int tid  = threadIdx.x;
    const int lane = tid & 31;
    const int g    = lane >> 2;
    const int q    = lane & 3;
    const int wrow = (tid >> 5) * 16;

    const unsigned* psrc[2]; unsigned pdst[2]; bool pact[2];
    #pragma unroll
    for (int rr = 0; rr < 2; rr++) {
        int idx = tid + 256*rr;
        pact[rr] = (idx < 384);
        int i2 = pact[rr] ? idx : 0;
        const unsigned* s;
        if      (i2 < 128) s = g_xb + ((size_t)(m0 + i2      )*16)*32;
        else if (i2 < 256) s = g_xr + ((size_t)(m0 + i2 - 128)*16)*32;
        else if (i2 < 320) s = g_wb + ((size_t)(mat*64 + i2 - 256)*16)*32;
        else               s = g_wr + ((size_t)(mat*64 + i2 - 320)*16)*32;
        psrc[rr] = s;
        pdst[rr] = (unsigned)i2 * (PCH*4);
    }

    #define QISSUE(c, st) do {                                                  \
        _Pragma("unroll")                                                        \
        for (int rr_ = 0; rr_ < 2; rr_++) if (pact[rr_]) {                      \
            const unsigned* sp_ = psrc[rr_] + (c)*32;                           \
            unsigned d_ = sbase + (unsigned)(st)*(QST*4u) + pdst[rr_];          \
            _Pragma("unroll")                                                    \
            for (int i_ = 0; i_ < 8; i_++) cp16(d_ + i_*16u, sp_ + i_*4);       \
        }                                                                        \
        asm volatile("cp.async.commit_group;");                                 \
    } while (0)

    float acc[8][4];
    #pragma unroll
    for (int j = 0; j < 8; j++)
        #pragma unroll
        for (int c = 0; c < 4; c++) acc[j][c] = 0.f;

    QISSUE(0, 0);
    for (int c = 0; c < 16; c++) {
        const int st = c & 1;
        if (c < 15) {
            QISSUE(c+1, st^1);
            asm volatile("cp.async.wait_group 1;");
        } else {
            asm volatile("cp.async.wait_group 0;");
        }
        __syncthreads();

        const unsigned* Xb = smu + st*QST;
        const unsigned* Xr = Xb + 128*PCH;
        const unsigned* Wb = Xb + 256*PCH;
        const unsigned* Wr = Xb + 320*PCH;

        #pragma unroll
        for (int ks = 0; ks < 4; ks++) {
            const int a0 = (wrow+g)*PCH + ks*8 + q*2;
            uint2 xAb = *(const uint2*)&Xb[a0];
            uint2 xBb = *(const uint2*)&Xb[a0 + 8*PCH];
            uint2 xAr = *(const uint2*)&Xr[a0];
            uint2 xBr = *(const uint2*)&Xr[a0 + 8*PCH];
            #pragma unroll
            for (int jn = 0; jn < 8; jn++) {
                const int bbo = (jn*8+g)*PCH + ks*8 + q*2;
                uint2 wb = *(const uint2*)&Wb[bbo];
                uint2 wr = *(const uint2*)&Wr[bbo];
                mma16816(acc[jn][0],acc[jn][1],acc[jn][2],acc[jn][3],
                         xAb.x,xBb.x,xAb.y,xBb.y, wb.x,wb.y);
                mma16816(acc[jn][0],acc[jn][1],acc[jn][2],acc[jn][3],
                         xAb.x,xBb.x,xAb.y,xBb.y, wr.x,wr.y);
                mma16816(acc[jn][0],acc[jn][1],acc[jn][2],acc[jn][3],
                         xAr.x,xBr.x,xAr.y,xBr.y, wb.x,wb.y);
            }
        }
        __syncthreads();
    }

    const float qscale = (mat == 1) ? 0.125f : 1.0f;
    #pragma unroll
    for (int jn = 0; jn < 8; jn++) {
        int col = jn*8 + q*2;
        float2 bb = *(const float2*)&bias[col];
        float o0 = fmaxf(acc[jn][0]+bb.x, 0.f) * qscale;
        float o1 = fmaxf(acc[jn][1]+bb.y, 0.f) * qscale;
        float o2 = fmaxf(acc[jn][2]+bb.x, 0.f) * qscale;
        float o3 = fmaxf(acc[jn][3]+bb.y, 0.f) * qscale;
        unsigned vb0, vr0, vb1, vr1;
        split2(o0, o1, vb0, vr0);
        split2(o2, o3, vb1, vr1);

        if (mat != 2) {
            unsigned* pb = (mat == 0) ? g_kb : g_qb;
            unsigned* pr = (mat == 0) ? g_kr : g_qr;
            int sl = slotf(jn*4 + q);
            size_t r0 = (size_t)(m0 + wrow + g);
            pb[r0*32 + sl]     = vb0;  pr[r0*32 + sl]     = vr0;
            pb[(r0+8)*32 + sl] = vb1;  pr[(r0+8)*32 + sl] = vr1;
        } else {
            unsigned ob0 = __shfl_xor_sync(0xffffffffu, vb0, 4);
            unsigned or0 = __shfl_xor_sync(0xffffffffu, vr0, 4);
            unsigned ob1 = __shfl_xor_sync(0xffffffffu, vb1, 4);
            unsigned or1 = __shfl_xor_sync(0xffffffffu, vr1, 4);
            unsigned rb0, rr0, rb1, rr1;
            if ((g & 1) == 0) {
                rb0 = prmtf(vb0, ob0, 0x5410); rr0 = prmtf(vr0, or0, 0x5410);
                rb1 = prmtf(vb1, ob1, 0x5410); rr1 = prmtf(vr1, or1, 0x5410);
            } else {
                rb0 = prmtf(ob0, vb0, 0x7632); rr0 = prmtf(or0, vr0, 0x7632);
                rb1 = prmtf(ob1, vb1, 0x7632); rr1 = prmtf(or1, vr1, 0x7632);
            }
            int d     = jn*8 + q*2 + (g & 1);
            int brow  = m0 / T;
            int base0 = (m0 & (T-1)) + wrow + (g & ~1);
            int tile  = base0 >> 6;
            int p0    = (base0 & 63) >> 1;
            size_t idx0 = ((size_t)(brow*64 + d))*(T/2) + tile*32 + slotf(p0);
            size_t idx1 = ((size_t)(brow*64 + d))*(T/2) + tile*32 + slotf(p0 + 4);
            g_vtb[idx0] = rb0;  g_vtr[idx0] = rr0;
            g_vtb[idx1] = rb1;  g_vtr[idx1] = rr1;
        }
    }
    #undef QISSUE
}

// ---------------------------------------------------------------------------
// Kernel 2: flash attention, 128q x AK=128 key tiles (halved softmax rounds).
// grid (T/128, NB) = 128 CTAs, block 256 (8 warps x 16 q-rows).
// Stage layout (u32): Kb[0,5120) Kr[5120,10240) Vb[10240,14848) Vr[14848,19456)
// K rows pitch 40; V rows pitch 72 (two 32-u32 halves per dim row).
// ---------------------------------------------------------------------------
#define VPCH 72
#define AST  19456                      // u32 per stage
#define ATTN_SMEM (2*AST*4)             // 155648 B

__global__ __launch_bounds__(256) void attn_kernel(float* __restrict__ out)
{
    extern __shared__ unsigned smu[];
    const unsigned sbase = smem_u32(smu);

    const int b    = blockIdx.y;
    const int q0   = blockIdx.x * 128;
    const int tid  = threadIdx.x;
    const int lane = tid & 31;
    const int g    = lane >> 2;
    const int q    = lane & 3;
    const int wrow = (tid >> 5) * 16;

    // producer: 512 units of 128B per tile; thread handles units tid, tid+256
    const unsigned* pb[2]; unsigned pd[2]; int pk[2];
    #pragma unroll
    for (int rr = 0; rr < 2; rr++) {
        int u = tid + 256*rr;
        if (u < 128)      { pb[rr] = g_kb + ((size_t)(b*T) + u)*32;       pd[rr] = u*PCH;                pk[rr] = 1; }
        else if (u < 256) { pb[rr] = g_kr + ((size_t)(b*T) + u-128)*32;   pd[rr] = 5120 + (u-128)*PCH;   pk[rr] = 1; }
        else if (u < 384) { int i=u-256, d=i>>1, h=i&1;
                            pb[rr] = g_vtb + ((size_t)(b*64 + d))*(T/2) + h*32;
                            pd[rr] = 10240 + d*VPCH + h*32;  pk[rr] = 0; }
        else              { int i=u-384, d=i>>1, h=i&1;
                            pb[rr] = g_vtr + ((size_t)(b*64 + d))*(T/2) + h*32;
                            pd[rr] = 14848 + d*VPCH + h*32;  pk[rr] = 0; }
        pd[rr] *= 4u;   // bytes
    }

    #define ISSUE(kt, stg) do {                                                 \
        _Pragma("unroll")                                                        \
        for (int rr_ = 0; rr_ < 2; rr_++) {                                     \
            const unsigned* sp_ = pb[rr_] + (pk[rr_] ? (size_t)(kt)*32          \
                                                     : (size_t)(kt)/2);         \
            unsigned d_ = sbase + (unsigned)(stg)*(AST*4u) + pd[rr_];           \
            _Pragma("unroll")                                                    \
            for (int i_ = 0; i_ < 8; i_++) cp16(d_ + i_*16u, sp_ + i_*4);       \
        }                                                                        \
        asm volatile("cp.async.commit_group;");                                 \
    } while (0)

    // Q fragments -> registers
    unsigned qb0[4],qb1[4],qb2[4],qb3[4], qr0[4],qr1[4],qr2[4],qr3[4];
    {
        ISSUE(0, 0);
        const size_t r0 = (size_t)(b*T + q0 + wrow + g);
        #pragma unroll
        for (int ks = 0; ks < 4; ks++) {
            uint2 a  = *(const uint2*)&g_qb[r0*32     + ks*8 + q*2];
            uint2 c  = *(const uint2*)&g_qb[(r0+8)*32 + ks*8 + q*2];
            qb0[ks]=a.x; qb2[ks]=a.y; qb1[ks]=c.x; qb3[ks]=c.y;
            uint2 ar = *(const uint2*)&g_qr[r0*32     + ks*8 + q*2];
            uint2 cr = *(const uint2*)&g_qr[(r0+8)*32 + ks*8 + q*2];
            qr0[ks]=ar.x; qr2[ks]=ar.y; qr1[ks]=cr.x; qr3[ks]=cr.y;
        }
    }

    float oacc[8][4];
    #pragma unroll
    for (int j = 0; j < 8; j++)
        #pragma unroll
        for (int c = 0; c < 4; c++) oacc[j][c] = 0.f;
    float m0 = -1e30f, m1 = -1e30f, l0 = 0.f, l1 = 0.f;

    int stg = 0;
    for (int kt = 0; kt < T; kt += 128) {
        if (kt + 128 < T) {
            ISSUE(kt + 128, stg ^ 1);
            asm volatile("cp.async.wait_group 1;");
        } else {
            asm volatile("cp.async.wait_group 0;");
        }
        __syncthreads();

        unsigned* Kb = smu + stg*AST;
        unsigned* Kr = Kb + 5120;
        unsigned* Vb = Kb + 10240;
        unsigned* Vr = Kb + 14848;

        // S = Q K^T over 128 keys (16 jn groups of 8)
        float s[16][4];
        #pragma unroll
        for (int j = 0; j < 16; j++)
            #pragma unroll
            for (int c = 0; c < 4; c++) s[j][c] = 0.f;

        #pragma unroll
        for (int ks = 0; ks < 4; ks++) {
            #pragma unroll
            for (int jn = 0; jn < 16; jn++) {
                const int bbo = (jn*8+g)*PCH + ks*8 + q*2;
                uint2 kb = *(const uint2*)&Kb[bbo];
                uint2 kr = *(const uint2*)&Kr[bbo];
                mma16816(s[jn][0],s[jn][1],s[jn][2],s[jn][3],
                         qb0[ks],qb1[ks],qb2[ks],qb3[ks], kb.x,kb.y);
                mma16816(s[jn][0],s[jn][1],s[jn][2],s[jn][3],
                         qb0[ks],qb1[ks],qb2[ks],qb3[ks], kr.x,kr.y);
                mma16816(s[jn][0],s[jn][1],s[jn][2],s[jn][3],
                         qr0[ks],qr1[ks],qr2[ks],qr3[ks], kb.x,kb.y);
            }
        }

        // online softmax over 128 keys
        float mx0 = -1e30f, mx1 = -1e30f;
        #pragma unroll
        for (int j = 0; j < 16; j++) {
            mx0 = fmaxf(mx0, fmaxf(s[j][0], s[j][1]));
            mx1 = fmaxf(mx1, fmaxf(s[j][2], s[j][3]));
        }
        mx0 = fmaxf(mx0, __shfl_xor_sync(0xffffffffu, mx0, 1));
        mx0 = fmaxf(mx0, __shfl_xor_sync(0xffffffffu, mx0, 2));
        mx1 = fmaxf(mx1, __shfl_xor_sync(0xffffffffu, mx1, 1));
        mx1 = fmaxf(mx1, __shfl_xor_sync(0xffffffffu, mx1, 2));
        float mn0 = fmaxf(m0, mx0), mn1 = fmaxf(m1, mx1);
        float al0 = __expf(m0 - mn0), al1 = __expf(m1 - mn1);
        m0 = mn0; m1 = mn1;

        float sum0 = 0.f, sum1 = 0.f;
        #pragma unroll
        for (int j = 0; j < 16; j++) {
            s[j][0] = __expf(s[j][0] - mn0);
            s[j][1] = __expf(s[j][1] - mn0);
            s[j][2] = __expf(s[j][2] - mn1);
            s[j][3] = __expf(s[j][3] - mn1);
            sum0 += s[j][0] + s[j][1];
            sum1 += s[j][2] + s[j][3];
        }
        sum0 += __shfl_xor_sync(0xffffffffu, sum0, 1);
        sum0 += __shfl_xor_sync(0xffffffffu, sum0, 2);
        sum1 += __shfl_xor_sync(0xffffffffu, sum1, 1);
        sum1 += __shfl_xor_sync(0xffffffffu, sum1, 2);
        l0 = l0*al0 + sum0;
        l1 = l1*al1 + sum1;
        #pragma unroll
        for (int j = 0; j < 8; j++) {
            oacc[j][0]*=al0; oacc[j][1]*=al0; oacc[j][2]*=al1; oacc[j][3]*=al1;
        }

        // O += P V  (8 k16 steps over 128 keys)
        #pragma unroll
        for (int kp = 0; kp < 8; kp++) {
            unsigned pb0,pr0,pb1,pr1,pb2,pr2,pb3,pr3;
            split2(s[2*kp  ][0], s[2*kp  ][1], pb0, pr0);
            split2(s[2*kp  ][2], s[2*kp  ][3], pb1, pr1);
            split2(s[2*kp+1][0], s[2*kp+1][1], pb2, pr2);
            split2(s[2*kp+1][2], s[2*kp+1][3], pb3, pr3);
            #pragma unroll
            for (int jn = 0; jn < 8; jn++) {
                const int vbo = (jn*8+g)*VPCH + kp*8 + q*2;
                uint2 vb = *(const uint2*)&Vb[vbo];
                uint2 vr = *(const uint2*)&Vr[vbo];
                mma16816(oacc[jn][0],oacc[jn][1],oacc[jn][2],oacc[jn][3],
                         pb0,pb1,pb2,pb3, vb.x,vb.y);
                mma16816(oacc[jn][0],oacc[jn][1],oacc[jn][2],oacc[jn][3],
                         pb0,pb1,pb2,pb3, vr.x,vr.y);
                mma16816(oacc[jn][0],oacc[jn][1],oacc[jn][2],oacc[jn][3],
                         pr0,pr1,pr2,pr3, vb.x,vb.y);
            }
        }
        __syncthreads();
        stg ^= 1;
    }

    float inv0 = 1.f / l0, inv1 = 1.f / l1;
    float* Og = out + ((size_t)b*T + q0)*DHEAD;
    #pragma unroll
    for (int jn = 0; jn < 8; jn++) {
        int col = jn*8 + q*2;
        int r0 = wrow + g;
        float2 o0 = make_float2(oacc[jn][0]*inv0, oacc[jn][1]*inv0);
        float2 o1 = make_float2(oacc[jn][2]*inv1, oacc[jn][3]*inv1);
        *(float2*)&Og[(size_t)r0*DHEAD + col]     = o0;
        *(float2*)&Og[(size_t)(r0+8)*DHEAD + col] = o1;
    }
    #undef ISSUE
}

// ---------------------------------------------------------------------------
extern "C" void kernel_launch(void* const* d_in, const int* in_sizes, int n_in,
                              void* d_out, int out_size)
{
    const float* x  = (const float*)d_in[0];
    const float* Wk = (const float*)d_in[1];
    const float* bk = (const float*)d_in[2];
    const float* Wq = (const float*)d_in[3];
    const float* bq = (const float*)d_in[4];
    const float* Wv = (const float*)d_in[5];
    const float* bv = (const float*)d_in[6];
    float* out = (float*)d_out;

    cudaFuncSetAttribute(qkv_kernel,
                         cudaFuncAttributeMaxDynamicSharedMemorySize, QKV_SMEM);
    cudaFuncSetAttribute(attn_kernel,
                         cudaFuncAttributeMaxDynamicSharedMemorySize, ATTN_SMEM);

    split_kernel<<<MT/8 + 24, 256>>>(x, Wk, Wq, Wv);

    dim3 g1(3, MT / 128);
    qkv_kernel<<<g1, 256, QKV_SMEM>>>(bk, bq, bv);

    dim3 g2(T / 128, NB);
    attn_kernel<<<g2, 256, ATTN_SMEM>>>(out);
}